// round 15
// baseline (speedup 1.0000x reference)
#include <cuda_runtime.h>
#include <math.h>

#define Bq 4
#define Lq 2048
#define Hq 8
#define Dq 64
#define NSLOT 12                 // self + offsets 2^0 .. 2^10
#define SLAB4 (Hq * Dq / 4)      // 128 x 16B chunks per (b,l) slab

// exp(score) = ex2(dot * 0.125 * log2(e))
#define EXC 0.18033688011112042f

__device__ __forceinline__ float ex2f(float x) {
    float r;
    asm("ex2.approx.f32 %0, %1;" : "=f"(r) : "f"(x));
    return r;
}

// One unit = (b, l, head-pair); lane ln owns 16B chunk ln of the 512B
// contiguous head-pair slab (lanes 0-15 even head, 16-31 odd head).
// NS = compile-time valid-slot count per tier; GEN = predicated path (l<64).
template <int NS, bool GEN>
__device__ __forceinline__ void run_query(
    const float4* __restrict__ Q4, const float4* __restrict__ K4,
    const float4* __restrict__ V4, float4* __restrict__ O4,
    int base, int l, int hl)     // hl = lane & 15
{
    const float4 q = Q4[base];

    // ---- phase 1: NS front-batched K loads, per-lane partial dots ----
    float v[16];
#pragma unroll
    for (int t = 0; t < NS; t++) {
        const int off = (t == 0) ? 0 : (1 << (t - 1));
        const bool ok = !GEN || (off <= l);
        const int kb = base - off * SLAB4;       // imm offset in tier paths
        float4 k = make_float4(0.f, 0.f, 0.f, 0.f);
        if (ok) k = K4[kb];
        v[t] = q.x*k.x + q.y*k.y + q.z*k.z + q.w*k.w;
    }
#pragma unroll
    for (int t = NS; t < 16; t++) v[t] = 0.0f;

    // ---- multi-value butterfly: 15 shfls reduce ALL slots; lane hl ends
    //      holding the full dot of slot hl ----
#pragma unroll
    for (int m = 8; m >= 1; m >>= 1) {
#pragma unroll
        for (int j = 0; j < m; j++) {
            const float send = (hl & m) ? v[j] : v[j + m];
            const float other = __shfl_xor_sync(0xffffffffu, send, m);
            v[j] = ((hl & m) ? v[j + m] : v[j]) + other;
        }
    }

    bool okl;
    if (!GEN) okl = (hl < NS);
    else      okl = (hl == 0) || ((hl < NSLOT) && ((1 << (hl - 1)) <= l));

    const float e = okl ? ex2f(v[0] * EXC) : 0.0f;

    // ---- phase 2: V gathers + width-16 prob broadcast; denominator summed
    //      locally from the broadcasts ----
    float4 acc = {0.f, 0.f, 0.f, 0.f};
    float  sum = 0.0f;
#pragma unroll
    for (int t = 0; t < NS; t++) {
        const int off = (t == 0) ? 0 : (1 << (t - 1));
        const bool ok = !GEN || (off <= l);
        const int vb = base - off * SLAB4;
        float4 vv = make_float4(0.f, 0.f, 0.f, 0.f);
        if (ok) vv = V4[vb];
        const float p = __shfl_sync(0xffffffffu, e, t, 16);
        sum += p;
        acc.x += p * vv.x;
        acc.y += p * vv.y;
        acc.z += p * vv.z;
        acc.w += p * vv.w;
    }
    const float inv = 1.0f / sum;
    acc.x *= inv; acc.y *= inv; acc.z *= inv; acc.w *= inv;
    O4[base] = acc;
}

__device__ __forceinline__ void dispatch_query(
    const float4* __restrict__ Q4, const float4* __restrict__ K4,
    const float4* __restrict__ V4, float4* __restrict__ O4,
    int base, int l, int hl)
{
    if      (l >= 1024) run_query<12, false>(Q4, K4, V4, O4, base, l, hl);
    else if (l >=  512) run_query<11, false>(Q4, K4, V4, O4, base, l, hl);
    else if (l >=  256) run_query<10, false>(Q4, K4, V4, O4, base, l, hl);
    else if (l >=  128) run_query< 9, false>(Q4, K4, V4, O4, base, l, hl);
    else if (l >=   64) run_query< 8, false>(Q4, K4, V4, O4, base, l, hl);
    else                run_query<12, true >(Q4, K4, V4, O4, base, l, hl);
}

// CTA c: 4 warps (one per head-pair g) x 2 sequential units at l = 2c%L and
// +1. Consecutive-l units share ~2-3 of 12 gathered K and V rows -> the
// second unit's overlapping gathers hit L1 (loaded by the same warp moments
// earlier; L1D persists within a launch).
__global__ __launch_bounds__(128) void logsparse_attn_kernel(
    const float4* __restrict__ Q4,
    const float4* __restrict__ K4,
    const float4* __restrict__ V4,
    float4* __restrict__ O4)
{
    const int tid  = threadIdx.x;
    const int lane = tid & 31;
    const int g    = tid >> 5;                   // head-pair 0..3
    const int s0   = blockIdx.x * 2;             // first unit: b*L + l
    const int l0   = s0 & (Lq - 1);

    const int base0 = s0 * SLAB4 + g * 32 + lane;
    const int hl = lane & 15;

    dispatch_query(Q4, K4, V4, O4, base0,         l0,     hl);
    dispatch_query(Q4, K4, V4, O4, base0 + SLAB4, l0 + 1, hl);   // l0+1 < Lq (s0 even)
}

extern "C" void kernel_launch(void* const* d_in, const int* in_sizes, int n_in,
                              void* d_out, int out_size)
{
    const float4* Q = (const float4*)d_in[0];
    const float4* K = (const float4*)d_in[1];
    const float4* V = (const float4*)d_in[2];
    float4* O = (float4*)d_out;

    const int blocks = (Bq * Lq) / 2;            // 4096 CTAs, 2 (b,l) each
    logsparse_attn_kernel<<<blocks, 128>>>(Q, K, V, O);
}